// round 3
// baseline (speedup 1.0000x reference)
#include <cuda_runtime.h>

// FWHT-128 over the last dim of three (4,32,4096,128) fp32 tensors.
// One warp per 128-float row; each lane holds a contiguous float4.
// Stages h=1,2 in-register; h=4,8,16,32,64 via __shfl_xor (lane masks 1..16).
// Output = concat(q', k', v') in d_out.

#define ROW_F4 32  // 128 floats = 32 float4 per row

__global__ __launch_bounds__(256) void fwht128_kernel(
    const float4* __restrict__ q,
    const float4* __restrict__ k,
    const float4* __restrict__ v,
    float4* __restrict__ out,
    int rowsPerArr)
{
    const int warp = (int)((blockIdx.x * blockDim.x + threadIdx.x) >> 5);
    const int lane = threadIdx.x & 31;
    if (warp >= rowsPerArr) return;

    const float4* __restrict__ src = (blockIdx.y == 0) ? q : (blockIdx.y == 1) ? k : v;

    const size_t idx = (size_t)warp * ROW_F4 + lane;
    float4 x = src[idx];

    // Stage h=1: pairs (0,1),(2,3) within the float4
    {
        float a0 = x.x, b0 = x.y;
        float a1 = x.z, b1 = x.w;
        x.x = a0 + b0; x.y = a0 - b0;
        x.z = a1 + b1; x.w = a1 - b1;
    }
    // Stage h=2: pairs (0,2),(1,3)
    {
        float a0 = x.x, b0 = x.z;
        float a1 = x.y, b1 = x.w;
        x.x = a0 + b0; x.z = a0 - b0;
        x.y = a1 + b1; x.w = a1 - b1;
    }
    // Stages h=4..64: partner lane = lane ^ m, m = h/4 in {1,2,4,8,16}
    #pragma unroll
    for (int m = 1; m <= 16; m <<= 1) {
        float yx = __shfl_xor_sync(0xffffffffu, x.x, m);
        float yy = __shfl_xor_sync(0xffffffffu, x.y, m);
        float yz = __shfl_xor_sync(0xffffffffu, x.z, m);
        float yw = __shfl_xor_sync(0xffffffffu, x.w, m);
        if (lane & m) {
            x.x = yx - x.x; x.y = yy - x.y;
            x.z = yz - x.z; x.w = yw - x.w;
        } else {
            x.x = x.x + yx; x.y = x.y + yy;
            x.z = x.z + yz; x.w = x.w + yw;
        }
    }

    const float s = 0.08838834764831845f;  // 1/sqrt(128)
    x.x *= s; x.y *= s; x.z *= s; x.w *= s;

    out[(size_t)blockIdx.y * rowsPerArr * ROW_F4 + idx] = x;
}

extern "C" void kernel_launch(void* const* d_in, const int* in_sizes, int n_in,
                              void* d_out, int out_size)
{
    const float4* q = (const float4*)d_in[0];
    const float4* k = (const float4*)d_in[1];
    const float4* v = (const float4*)d_in[2];
    float4* out = (float4*)d_out;

    const int rowsPerArr = in_sizes[0] / 128;        // 524288
    const int warpsPerBlock = 256 / 32;              // 8 rows per block
    const int blocksX = (rowsPerArr + warpsPerBlock - 1) / warpsPerBlock;

    dim3 grid(blocksX, 3, 1);
    fwht128_kernel<<<grid, 256>>>(q, k, v, out, rowsPerArr);
}

// round 4
// speedup vs baseline: 1.0951x; 1.0951x over previous
#include <cuda_runtime.h>

// FWHT-128 over the last dim of three (4,32,4096,128) fp32 tensors.
// Layout: 8 lanes per row, 4 rows per warp. Each thread owns 16 floats of one
// row as 4 float4s at float4-indices {j, j+8, j+16, j+24} (j = lane&7), i.e.
// floats 4j+{0..3} + {0,32,64,96}.
//   In-register stages: h=1,2 (inside float4), h=32,64 (across the 4 float4s).
//   Shuffle stages:     h=4,8,16 -> __shfl_xor masks 1,2,4 (within 8-lane group).
// 4 front-batched LDG.128 per thread (MLP=4); streaming cache hints.

__global__ __launch_bounds__(256) void fwht128_kernel(
    const float4* __restrict__ q,
    const float4* __restrict__ k,
    const float4* __restrict__ v,
    float4* __restrict__ out,
    int rowsPerArr)
{
    const int lane = threadIdx.x & 31;
    const int warpGlobal = (int)((blockIdx.x * blockDim.x + threadIdx.x) >> 5);
    const int row = warpGlobal * 4 + (lane >> 3);
    if (row >= rowsPerArr) return;

    const float4* __restrict__ src = (blockIdx.y == 0) ? q : (blockIdx.y == 1) ? k : v;

    const size_t base = (size_t)row * 32 + (lane & 7);

    // Front-batched independent loads (MLP = 4), streaming hint.
    float4 f0 = __ldcs(src + base);
    float4 f1 = __ldcs(src + base + 8);
    float4 f2 = __ldcs(src + base + 16);
    float4 f3 = __ldcs(src + base + 24);

    // ---- Stage h=1: pairs (x,y),(z,w) inside each float4 ----
    #define STAGE_H1(f) { float a=f.x, b=f.y, c=f.z, d=f.w; \
        f.x=a+b; f.y=a-b; f.z=c+d; f.w=c-d; }
    STAGE_H1(f0) STAGE_H1(f1) STAGE_H1(f2) STAGE_H1(f3)

    // ---- Stage h=2: pairs (x,z),(y,w) inside each float4 ----
    #define STAGE_H2(f) { float a=f.x, b=f.z, c=f.y, d=f.w; \
        f.x=a+b; f.z=a-b; f.y=c+d; f.w=c-d; }
    STAGE_H2(f0) STAGE_H2(f1) STAGE_H2(f2) STAGE_H2(f3)

    // ---- Stages h=4,8,16: partner lane = lane ^ m, m in {1,2,4} ----
    #pragma unroll
    for (int m = 1; m <= 4; m <<= 1) {
        const bool hi = (lane & m) != 0;
        #define SHFL_BF(val) { \
            float p = __shfl_xor_sync(0xffffffffu, val, m); \
            val = hi ? (p - val) : (val + p); }
        SHFL_BF(f0.x) SHFL_BF(f0.y) SHFL_BF(f0.z) SHFL_BF(f0.w)
        SHFL_BF(f1.x) SHFL_BF(f1.y) SHFL_BF(f1.z) SHFL_BF(f1.w)
        SHFL_BF(f2.x) SHFL_BF(f2.y) SHFL_BF(f2.z) SHFL_BF(f2.w)
        SHFL_BF(f3.x) SHFL_BF(f3.y) SHFL_BF(f3.z) SHFL_BF(f3.w)
        #undef SHFL_BF
    }

    // ---- Stage h=32: (f0,f1), (f2,f3) ----
    #define BF_PAIR(a, b) { float ta; \
        ta=a.x; a.x=ta+b.x; b.x=ta-b.x; \
        ta=a.y; a.y=ta+b.y; b.y=ta-b.y; \
        ta=a.z; a.z=ta+b.z; b.z=ta-b.z; \
        ta=a.w; a.w=ta+b.w; b.w=ta-b.w; }
    BF_PAIR(f0, f1)
    BF_PAIR(f2, f3)

    // ---- Stage h=64: (f0,f2), (f1,f3) ----
    BF_PAIR(f0, f2)
    BF_PAIR(f1, f3)

    // ---- Scale by 1/sqrt(128) ----
    const float s = 0.08838834764831845f;
    #define SCALE(f) { f.x*=s; f.y*=s; f.z*=s; f.w*=s; }
    SCALE(f0) SCALE(f1) SCALE(f2) SCALE(f3)

    float4* __restrict__ dst = out + (size_t)blockIdx.y * rowsPerArr * 32;
    __stcs(dst + base,      f0);
    __stcs(dst + base + 8,  f1);
    __stcs(dst + base + 16, f2);
    __stcs(dst + base + 24, f3);
}

extern "C" void kernel_launch(void* const* d_in, const int* in_sizes, int n_in,
                              void* d_out, int out_size)
{
    const float4* q = (const float4*)d_in[0];
    const float4* k = (const float4*)d_in[1];
    const float4* v = (const float4*)d_in[2];
    float4* out = (float4*)d_out;

    const int rowsPerArr = in_sizes[0] / 128;   // 524288
    const int rowsPerBlock = (256 / 32) * 4;    // 8 warps * 4 rows = 32
    const int blocksX = (rowsPerArr + rowsPerBlock - 1) / rowsPerBlock;

    dim3 grid(blocksX, 3, 1);
    fwht128_kernel<<<grid, 256>>>(q, k, v, out, rowsPerArr);
}

// round 5
// speedup vs baseline: 1.0992x; 1.0037x over previous
#include <cuda_runtime.h>

// FWHT-128 over the last dim of three (4,32,4096,128) fp32 tensors.
// Layout: 4 lanes per row, 8 rows per warp. Thread (j = lane&3) owns 32 floats
// of its row as 8 float4s at float4-indices {j + 4k, k=0..7}, i.e. element
// offsets e = 16k + 4j + m.
//   In-register stages: h=1,2 (inside each float4),
//                       h=16,32,64 (bits 0,1,2 of k -> pair butterflies).
//   Shuffle stages:     h=4,8 -> __shfl_xor masks 1,2 (within 4-lane group).
// 8 front-batched LDG.128 per thread (MLP=8); streaming cache hints.

__global__ __launch_bounds__(256) void fwht128_kernel(
    const float4* __restrict__ q,
    const float4* __restrict__ k,
    const float4* __restrict__ v,
    float4* __restrict__ out,
    int rowsPerArr)
{
    const int lane = threadIdx.x & 31;
    const int warpGlobal = (int)((blockIdx.x * blockDim.x + threadIdx.x) >> 5);
    const int row = warpGlobal * 8 + (lane >> 2);
    if (row >= rowsPerArr) return;

    const float4* __restrict__ src = (blockIdx.y == 0) ? q : (blockIdx.y == 1) ? k : v;

    const size_t base = (size_t)row * 32 + (lane & 3);

    // Front-batched independent loads (MLP = 8), streaming hint.
    float4 f0 = __ldcs(src + base);
    float4 f1 = __ldcs(src + base + 4);
    float4 f2 = __ldcs(src + base + 8);
    float4 f3 = __ldcs(src + base + 12);
    float4 f4 = __ldcs(src + base + 16);
    float4 f5 = __ldcs(src + base + 20);
    float4 f6 = __ldcs(src + base + 24);
    float4 f7 = __ldcs(src + base + 28);

    // ---- Stage h=1: pairs (x,y),(z,w) inside each float4 ----
    #define STAGE_H1(f) { float a=f.x, b=f.y, c=f.z, d=f.w; \
        f.x=a+b; f.y=a-b; f.z=c+d; f.w=c-d; }
    STAGE_H1(f0) STAGE_H1(f1) STAGE_H1(f2) STAGE_H1(f3)
    STAGE_H1(f4) STAGE_H1(f5) STAGE_H1(f6) STAGE_H1(f7)

    // ---- Stage h=2: pairs (x,z),(y,w) inside each float4 ----
    #define STAGE_H2(f) { float a=f.x, b=f.z, c=f.y, d=f.w; \
        f.x=a+b; f.z=a-b; f.y=c+d; f.w=c-d; }
    STAGE_H2(f0) STAGE_H2(f1) STAGE_H2(f2) STAGE_H2(f3)
    STAGE_H2(f4) STAGE_H2(f5) STAGE_H2(f6) STAGE_H2(f7)

    // ---- Stages h=4,8: partner lane = lane ^ m, m in {1,2} ----
    // val_new = p + sgn*val  (sgn=+1 on low side: val+p; sgn=-1 on high: p-val)
    #pragma unroll
    for (int m = 1; m <= 2; m <<= 1) {
        const float sgn = (lane & m) ? -1.0f : 1.0f;
        #define SHFL_BF(val) { \
            float p = __shfl_xor_sync(0xffffffffu, val, m); \
            val = fmaf(val, sgn, p); }
        SHFL_BF(f0.x) SHFL_BF(f0.y) SHFL_BF(f0.z) SHFL_BF(f0.w)
        SHFL_BF(f1.x) SHFL_BF(f1.y) SHFL_BF(f1.z) SHFL_BF(f1.w)
        SHFL_BF(f2.x) SHFL_BF(f2.y) SHFL_BF(f2.z) SHFL_BF(f2.w)
        SHFL_BF(f3.x) SHFL_BF(f3.y) SHFL_BF(f3.z) SHFL_BF(f3.w)
        SHFL_BF(f4.x) SHFL_BF(f4.y) SHFL_BF(f4.z) SHFL_BF(f4.w)
        SHFL_BF(f5.x) SHFL_BF(f5.y) SHFL_BF(f5.z) SHFL_BF(f5.w)
        SHFL_BF(f6.x) SHFL_BF(f6.y) SHFL_BF(f6.z) SHFL_BF(f6.w)
        SHFL_BF(f7.x) SHFL_BF(f7.y) SHFL_BF(f7.z) SHFL_BF(f7.w)
        #undef SHFL_BF
    }

    // ---- Pair butterfly across float4s ----
    #define BF_PAIR(a, b) { float ta; \
        ta=a.x; a.x=ta+b.x; b.x=ta-b.x; \
        ta=a.y; a.y=ta+b.y; b.y=ta-b.y; \
        ta=a.z; a.z=ta+b.z; b.z=ta-b.z; \
        ta=a.w; a.w=ta+b.w; b.w=ta-b.w; }

    // Stage h=16: bit0 of k -> (f0,f1),(f2,f3),(f4,f5),(f6,f7)
    BF_PAIR(f0, f1) BF_PAIR(f2, f3) BF_PAIR(f4, f5) BF_PAIR(f6, f7)
    // Stage h=32: bit1 of k -> (f0,f2),(f1,f3),(f4,f6),(f5,f7)
    BF_PAIR(f0, f2) BF_PAIR(f1, f3) BF_PAIR(f4, f6) BF_PAIR(f5, f7)
    // Stage h=64: bit2 of k -> (f0,f4),(f1,f5),(f2,f6),(f3,f7)
    BF_PAIR(f0, f4) BF_PAIR(f1, f5) BF_PAIR(f2, f6) BF_PAIR(f3, f7)

    // ---- Scale by 1/sqrt(128) ----
    const float s = 0.08838834764831845f;
    #define SCALE(f) { f.x*=s; f.y*=s; f.z*=s; f.w*=s; }
    SCALE(f0) SCALE(f1) SCALE(f2) SCALE(f3)
    SCALE(f4) SCALE(f5) SCALE(f6) SCALE(f7)

    float4* __restrict__ dst = out + (size_t)blockIdx.y * rowsPerArr * 32;
    __stcs(dst + base,      f0);
    __stcs(dst + base + 4,  f1);
    __stcs(dst + base + 8,  f2);
    __stcs(dst + base + 12, f3);
    __stcs(dst + base + 16, f4);
    __stcs(dst + base + 20, f5);
    __stcs(dst + base + 24, f6);
    __stcs(dst + base + 28, f7);
}

extern "C" void kernel_launch(void* const* d_in, const int* in_sizes, int n_in,
                              void* d_out, int out_size)
{
    const float4* q = (const float4*)d_in[0];
    const float4* k = (const float4*)d_in[1];
    const float4* v = (const float4*)d_in[2];
    float4* out = (float4*)d_out;

    const int rowsPerArr = in_sizes[0] / 128;   // 524288
    const int rowsPerBlock = (256 / 32) * 8;    // 8 warps * 8 rows = 64
    const int blocksX = (rowsPerArr + rowsPerBlock - 1) / rowsPerBlock;

    dim3 grid(blocksX, 3, 1);
    fwht128_kernel<<<grid, 256>>>(q, k, v, out, rowsPerArr);
}